// round 1
// baseline (speedup 1.0000x reference)
#include <cuda_runtime.h>
#include <math.h>

#define Bn 1024
#define Rn 512
#define Dn 128
#define On 64

// hyperparameters
#define BETA   6.5f
#define LAM_A  0.0033f
#define LAM_W  0.003f

// ---------------- scratch (device globals; no allocation allowed) -------------
__device__ __align__(16) float g_S[Bn * Rn];     // s[b,r] = exp(-beta*d)
__device__ __align__(16) float g_SB[Bn * Rn];    // beta*s*0.5/d
__device__ __align__(16) float g_G[Bn * On];     // dL/dx_out
__device__ __align__(16) float g_coef[Bn * Rn];  // -T[b,r]*SB[b,r]

// ================= K1: RBF activations s[b,r] ==================================
// block tile 64 r x 64 b, 256 threads, 4x4 micro-tile, D tiled by 32.
__global__ void __launch_bounds__(256) k1_rbf(const float* __restrict__ z,
                                              const float* __restrict__ attn,
                                              const float* __restrict__ rbf)
{
    __shared__ float sr[64][33];
    __shared__ float sz[64][33];
    __shared__ float sa[64][33];

    const int tid  = threadIdx.x;
    const int tr   = tid & 15;      // r lane
    const int tb   = tid >> 4;      // b lane
    const int rblk = blockIdx.x << 6;
    const int bblk = blockIdx.y << 6;

    float acc[4][4];
#pragma unroll
    for (int i = 0; i < 4; ++i)
#pragma unroll
        for (int j = 0; j < 4; ++j) acc[i][j] = 0.f;

    const int lrow = tid >> 2;          // 0..63
    const int lcol = (tid & 3) << 3;    // 0,8,16,24

    for (int kc = 0; kc < 4; ++kc) {
        __syncthreads();
        const int goff = kc * 32 + lcol;
        float4 r0 = *(const float4*)(rbf  + (rblk + lrow) * Dn + goff);
        float4 r1 = *(const float4*)(rbf  + (rblk + lrow) * Dn + goff + 4);
        float4 z0 = *(const float4*)(z    + (bblk + lrow) * Dn + goff);
        float4 z1 = *(const float4*)(z    + (bblk + lrow) * Dn + goff + 4);
        float4 a0 = *(const float4*)(attn + (bblk + lrow) * Dn + goff);
        float4 a1 = *(const float4*)(attn + (bblk + lrow) * Dn + goff + 4);
        sr[lrow][lcol + 0] = r0.x; sr[lrow][lcol + 1] = r0.y;
        sr[lrow][lcol + 2] = r0.z; sr[lrow][lcol + 3] = r0.w;
        sr[lrow][lcol + 4] = r1.x; sr[lrow][lcol + 5] = r1.y;
        sr[lrow][lcol + 6] = r1.z; sr[lrow][lcol + 7] = r1.w;
        sz[lrow][lcol + 0] = z0.x; sz[lrow][lcol + 1] = z0.y;
        sz[lrow][lcol + 2] = z0.z; sz[lrow][lcol + 3] = z0.w;
        sz[lrow][lcol + 4] = z1.x; sz[lrow][lcol + 5] = z1.y;
        sz[lrow][lcol + 6] = z1.z; sz[lrow][lcol + 7] = z1.w;
        sa[lrow][lcol + 0] = a0.x; sa[lrow][lcol + 1] = a0.y;
        sa[lrow][lcol + 2] = a0.z; sa[lrow][lcol + 3] = a0.w;
        sa[lrow][lcol + 4] = a1.x; sa[lrow][lcol + 5] = a1.y;
        sa[lrow][lcol + 6] = a1.z; sa[lrow][lcol + 7] = a1.w;
        __syncthreads();

#pragma unroll 4
        for (int d = 0; d < 32; ++d) {
            float rv[4], zv[4], av[4];
#pragma unroll
            for (int i = 0; i < 4; ++i) rv[i] = sr[tr + 16 * i][d];
#pragma unroll
            for (int j = 0; j < 4; ++j) { zv[j] = sz[tb + 16 * j][d]; av[j] = sa[tb + 16 * j][d]; }
#pragma unroll
            for (int j = 0; j < 4; ++j)
#pragma unroll
                for (int i = 0; i < 4; ++i) {
                    float t = zv[j] - rv[i];
                    acc[i][j] = fmaf(av[j] * t, t, acc[i][j]);
                }
        }
    }

#pragma unroll
    for (int j = 0; j < 4; ++j) {
        const int b = bblk + tb + 16 * j;
#pragma unroll
        for (int i = 0; i < 4; ++i) {
            const int r = rblk + tr + 16 * i;
            float d2 = acc[i][j];
            float dd = sqrtf(d2);
            float s  = expf(-BETA * dd);
            g_S[b * Rn + r]  = s;
            g_SB[b * Rn + r] = (0.5f * BETA) * s / dd;
        }
    }
}

// ================= K2: x_out, teacher error G =================================
// one block per batch; reads assoc row-block (128KB), reduces over r.
__global__ void __launch_bounds__(256) k2_xout(const float* __restrict__ assoc,
                                               const float* __restrict__ onehot,
                                               float* __restrict__ out_x)
{
    __shared__ float sS[Rn];
    __shared__ __align__(16) float4 part[16][16];

    const int b   = blockIdx.x;
    const int tid = threadIdx.x;
    sS[tid]       = g_S[b * Rn + tid];
    sS[tid + 256] = g_S[b * Rn + tid + 256];
    __syncthreads();

    const int oq = tid & 15;   // o quad
    const int rg = tid >> 4;   // r group
    float4 acc = make_float4(0.f, 0.f, 0.f, 0.f);
    const float4* arow = (const float4*)assoc + (size_t)b * (Rn * On / 4);

#pragma unroll 4
    for (int r = rg; r < Rn; r += 16) {
        float  s = sS[r];
        float4 a = arow[r * 16 + oq];
        acc.x = fmaf(s, a.x, acc.x);
        acc.y = fmaf(s, a.y, acc.y);
        acc.z = fmaf(s, a.z, acc.z);
        acc.w = fmaf(s, a.w, acc.w);
    }
    part[rg][oq] = acc;
    __syncthreads();

    if (rg == 0) {
        float4 t = part[0][oq];
#pragma unroll
        for (int k = 1; k < 16; ++k) {
            float4 p = part[k][oq];
            t.x += p.x; t.y += p.y; t.z += p.z; t.w += p.w;
        }
        float xs[4] = {t.x, t.y, t.z, t.w};
#pragma unroll
        for (int c = 0; c < 4; ++c) {
            const int o = oq * 4 + c;
            float x   = xs[c];
            float lab = onehot[b * On + o];
            float tmin  = fminf(-1.f, x);
            float teach = tmin - lab * tmin + lab * fmaxf(1.f, x);
            float e  = teach - x;
            float gd = (1.f - lab) * (x < -1.f ? 1.f : 0.f) + lab * (x > 1.f ? 1.f : 0.f);
            float G  = 0.03125f * e * (gd - 1.f);   // (2/O)*e*(dT/dx - 1)
            g_G[b * On + o]   = G;
            out_x[b * On + o] = 2.f * x;            // PHI = 2
        }
    }
}

// ================= K3: assoc update + dL/ds (fused) ===========================
// each half-warp handles one (b,r) row of 64 floats (float4/lane).
__global__ void __launch_bounds__(256) k3_assoc(const float* __restrict__ assoc,
                                                float* __restrict__ out_assoc)
{
    const int lane = threadIdx.x & 31;
    const int half = lane >> 4;
    const int l    = lane & 15;
    const int gw   = (blockIdx.x * blockDim.x + threadIdx.x) >> 5;
    const int nw   = (gridDim.x * blockDim.x) >> 5;

    for (int row = gw * 2 + half; row < Bn * Rn; row += nw * 2) {
        const int b = row >> 9;
        const float4 a = ((const float4*)assoc)[(size_t)row * 16 + l];
        const float4 g = ((const float4*)g_G)[b * 16 + l];

        float dot = a.x * g.x;
        dot = fmaf(a.y, g.y, dot);
        dot = fmaf(a.z, g.z, dot);
        dot = fmaf(a.w, g.w, dot);
        dot += __shfl_xor_sync(0xffffffffu, dot, 8);
        dot += __shfl_xor_sync(0xffffffffu, dot, 4);
        dot += __shfl_xor_sync(0xffffffffu, dot, 2);
        dot += __shfl_xor_sync(0xffffffffu, dot, 1);

        const float sc = LAM_W * g_S[row];
        float4 o4;
        o4.x = fmaf(-sc, g.x, a.x);
        o4.y = fmaf(-sc, g.y, a.y);
        o4.z = fmaf(-sc, g.z, a.z);
        o4.w = fmaf(-sc, g.w, a.w);
        ((float4*)out_assoc)[(size_t)row * 16 + l] = o4;

        if (l == 0) g_coef[row] = -dot * g_SB[row];
    }
}

// ================= K4: attention gradient + update ============================
// block handles 8 batches; 256 threads = 128 dims x 2 r-halves.
__global__ void __launch_bounds__(256) k4_attn(const float* __restrict__ z,
                                               const float* __restrict__ attn,
                                               const float* __restrict__ rbf,
                                               float* __restrict__ out_attn)
{
    __shared__ __align__(16) float sc[8][512];
    __shared__ float sred[8][128];

    const int tid  = threadIdx.x;
    const int j    = tid & 127;
    const int rh   = tid >> 7;
    const int bblk = blockIdx.x << 3;

    for (int idx = tid; idx < 8 * 512; idx += 256) {
        const int tb = idx >> 9;
        const int r  = idx & 511;
        sc[tb][r] = g_coef[(bblk + tb) * Rn + r];
    }
    float zr[8];
#pragma unroll
    for (int tb = 0; tb < 8; ++tb) zr[tb] = z[(bblk + tb) * Dn + j];
    __syncthreads();

    float acc[8];
#pragma unroll
    for (int tb = 0; tb < 8; ++tb) acc[tb] = 0.f;

    const int r0 = rh * 256;
#pragma unroll 2
    for (int r = r0; r < r0 + 256; r += 4) {
        const float rv0 = rbf[(r + 0) * Dn + j];
        const float rv1 = rbf[(r + 1) * Dn + j];
        const float rv2 = rbf[(r + 2) * Dn + j];
        const float rv3 = rbf[(r + 3) * Dn + j];
#pragma unroll
        for (int tb = 0; tb < 8; ++tb) {
            const float4 c = *(const float4*)&sc[tb][r];
            float t;
            t = zr[tb] - rv0; acc[tb] = fmaf(c.x * t, t, acc[tb]);
            t = zr[tb] - rv1; acc[tb] = fmaf(c.y * t, t, acc[tb]);
            t = zr[tb] - rv2; acc[tb] = fmaf(c.z * t, t, acc[tb]);
            t = zr[tb] - rv3; acc[tb] = fmaf(c.w * t, t, acc[tb]);
        }
    }

    if (rh == 1) {
#pragma unroll
        for (int tb = 0; tb < 8; ++tb) sred[tb][j] = acc[tb];
    }
    __syncthreads();
    if (rh == 0) {
#pragma unroll
        for (int tb = 0; tb < 8; ++tb) {
            const int b = bblk + tb;
            const float dl = acc[tb] + sred[tb][j];
            out_attn[b * Dn + j] = fmaxf(fmaf(-LAM_A, dl, attn[b * Dn + j]), 0.f);
        }
    }
}

// ================= launch ======================================================
extern "C" void kernel_launch(void* const* d_in, const int* in_sizes, int n_in,
                              void* d_out, int out_size)
{
    const float* z      = (const float*)d_in[0];  // (B,D)
    const float* onehot = (const float*)d_in[1];  // (B,O)
    const float* attn   = (const float*)d_in[2];  // (B,D)
    const float* assoc  = (const float*)d_in[3];  // (B,R,O)
    const float* rbf    = (const float*)d_in[4];  // (R,D)

    float* out       = (float*)d_out;
    float* out_x     = out;                 // B*O
    float* out_attn  = out + Bn * On;       // B*D
    float* out_assoc = out + Bn * On + Bn * Dn;  // B*R*O

    k1_rbf  <<<dim3(Rn / 64, Bn / 64), 256>>>(z, attn, rbf);
    k2_xout <<<Bn, 256>>>(assoc, onehot, out_x);
    k3_assoc<<<2048, 256>>>(assoc, out_assoc);
    k4_attn <<<Bn / 8, 256>>>(z, attn, rbf, out_attn);
}

// round 2
// speedup vs baseline: 1.0407x; 1.0407x over previous
#include <cuda_runtime.h>
#include <math.h>

#define Bn 1024
#define Rn 512
#define Dn 128
#define On 64

#define BETA   6.5f
#define LAM_A  0.0033f
#define LAM_W  0.003f

// ---------------- scratch (device globals; no allocation allowed) -------------
__device__ __align__(16) float g_S[Bn * Rn];     // s[b,r] = exp(-beta*d)
__device__ __align__(16) float g_SB[Bn * Rn];    // beta*s*0.5/d
__device__ __align__(16) float g_G[Bn * On];     // dL/dx_out
__device__ __align__(16) float g_coef[Bn * Rn];  // -T[b,r]*SB[b,r]

// ================= K1: RBF activations s[b,r] ==================================
// block tile 64 r x 32 b, 256 threads, 4x2 micro-tile, D tiled by 32.
// grid = (512/64) x (1024/32) = 8 x 32 = 256 blocks.
__global__ void __launch_bounds__(256) k1_rbf(const float* __restrict__ z,
                                              const float* __restrict__ attn,
                                              const float* __restrict__ rbf)
{
    __shared__ float sr[64][33];
    __shared__ float sz[32][33];
    __shared__ float sa[32][33];

    const int tid  = threadIdx.x;
    const int tr   = tid & 15;      // r lane
    const int tb   = tid >> 4;      // b lane (0..15)
    const int rblk = blockIdx.x << 6;
    const int bblk = blockIdx.y << 5;

    float acc[4][2];
#pragma unroll
    for (int i = 0; i < 4; ++i)
#pragma unroll
        for (int j = 0; j < 2; ++j) acc[i][j] = 0.f;

    // rbf loader mapping: 64 rows x 32 cols = 2048 floats, 8 per thread
    const int lrowR = tid >> 2;          // 0..63
    const int lcolR = (tid & 3) << 3;    // 0,8,16,24
    // z/attn loader mapping: 32 rows x 32 cols = 1024 floats, 4 per thread
    const int lrowB = tid >> 3;          // 0..31
    const int lcolB = (tid & 7) << 2;    // 0..28

    for (int kc = 0; kc < 4; ++kc) {
        __syncthreads();
        const int goffR = kc * 32 + lcolR;
        float4 r0 = *(const float4*)(rbf + (rblk + lrowR) * Dn + goffR);
        float4 r1 = *(const float4*)(rbf + (rblk + lrowR) * Dn + goffR + 4);
        const int goffB = kc * 32 + lcolB;
        float4 z0 = *(const float4*)(z    + (bblk + lrowB) * Dn + goffB);
        float4 a0 = *(const float4*)(attn + (bblk + lrowB) * Dn + goffB);

        sr[lrowR][lcolR + 0] = r0.x; sr[lrowR][lcolR + 1] = r0.y;
        sr[lrowR][lcolR + 2] = r0.z; sr[lrowR][lcolR + 3] = r0.w;
        sr[lrowR][lcolR + 4] = r1.x; sr[lrowR][lcolR + 5] = r1.y;
        sr[lrowR][lcolR + 6] = r1.z; sr[lrowR][lcolR + 7] = r1.w;
        sz[lrowB][lcolB + 0] = z0.x; sz[lrowB][lcolB + 1] = z0.y;
        sz[lrowB][lcolB + 2] = z0.z; sz[lrowB][lcolB + 3] = z0.w;
        sa[lrowB][lcolB + 0] = a0.x; sa[lrowB][lcolB + 1] = a0.y;
        sa[lrowB][lcolB + 2] = a0.z; sa[lrowB][lcolB + 3] = a0.w;
        __syncthreads();

#pragma unroll 4
        for (int d = 0; d < 32; ++d) {
            float rv[4], zv[2], av[2];
#pragma unroll
            for (int i = 0; i < 4; ++i) rv[i] = sr[tr + 16 * i][d];
#pragma unroll
            for (int j = 0; j < 2; ++j) { zv[j] = sz[tb + 16 * j][d]; av[j] = sa[tb + 16 * j][d]; }
#pragma unroll
            for (int j = 0; j < 2; ++j)
#pragma unroll
                for (int i = 0; i < 4; ++i) {
                    float t = zv[j] - rv[i];
                    acc[i][j] = fmaf(av[j] * t, t, acc[i][j]);
                }
        }
    }

#pragma unroll
    for (int j = 0; j < 2; ++j) {
        const int b = bblk + tb + 16 * j;
#pragma unroll
        for (int i = 0; i < 4; ++i) {
            const int r = rblk + tr + 16 * i;
            float d2 = acc[i][j];
            float dd = sqrtf(d2);
            float s  = expf(-BETA * dd);
            g_S[b * Rn + r]  = s;
            g_SB[b * Rn + r] = (0.5f * BETA) * s / dd;
        }
    }
}

// ================= K2: x_out, teacher error G =================================
__global__ void __launch_bounds__(256) k2_xout(const float* __restrict__ assoc,
                                               const float* __restrict__ onehot,
                                               float* __restrict__ out_x)
{
    __shared__ float sS[Rn];
    __shared__ __align__(16) float4 part[16][16];

    const int b   = blockIdx.x;
    const int tid = threadIdx.x;
    sS[tid]       = g_S[b * Rn + tid];
    sS[tid + 256] = g_S[b * Rn + tid + 256];
    __syncthreads();

    const int oq = tid & 15;   // o quad
    const int rg = tid >> 4;   // r group
    float4 acc = make_float4(0.f, 0.f, 0.f, 0.f);
    const float4* arow = (const float4*)assoc + (size_t)b * (Rn * On / 4);

#pragma unroll 4
    for (int r = rg; r < Rn; r += 16) {
        float  s = sS[r];
        float4 a = arow[r * 16 + oq];
        acc.x = fmaf(s, a.x, acc.x);
        acc.y = fmaf(s, a.y, acc.y);
        acc.z = fmaf(s, a.z, acc.z);
        acc.w = fmaf(s, a.w, acc.w);
    }
    part[rg][oq] = acc;
    __syncthreads();

    if (rg == 0) {
        float4 t = part[0][oq];
#pragma unroll
        for (int k = 1; k < 16; ++k) {
            float4 p = part[k][oq];
            t.x += p.x; t.y += p.y; t.z += p.z; t.w += p.w;
        }
        float xs[4] = {t.x, t.y, t.z, t.w};
#pragma unroll
        for (int c = 0; c < 4; ++c) {
            const int o = oq * 4 + c;
            float x   = xs[c];
            float lab = onehot[b * On + o];
            float tmin  = fminf(-1.f, x);
            float teach = tmin - lab * tmin + lab * fmaxf(1.f, x);
            float e  = teach - x;
            float gd = (1.f - lab) * (x < -1.f ? 1.f : 0.f) + lab * (x > 1.f ? 1.f : 0.f);
            float G  = 0.03125f * e * (gd - 1.f);   // (2/O)*e*(dT/dx - 1)
            g_G[b * On + o]   = G;
            out_x[b * On + o] = 2.f * x;            // PHI = 2
        }
    }
}

// ================= K3: assoc update + dL/ds (fused) ===========================
__global__ void __launch_bounds__(256) k3_assoc(const float* __restrict__ assoc,
                                                float* __restrict__ out_assoc)
{
    const int lane = threadIdx.x & 31;
    const int half = lane >> 4;
    const int l    = lane & 15;
    const int gw   = (blockIdx.x * blockDim.x + threadIdx.x) >> 5;
    const int nw   = (gridDim.x * blockDim.x) >> 5;

    for (int row = gw * 2 + half; row < Bn * Rn; row += nw * 2) {
        const int b = row >> 9;
        const float4 a = ((const float4*)assoc)[(size_t)row * 16 + l];
        const float4 g = ((const float4*)g_G)[b * 16 + l];

        float dot = a.x * g.x;
        dot = fmaf(a.y, g.y, dot);
        dot = fmaf(a.z, g.z, dot);
        dot = fmaf(a.w, g.w, dot);
        dot += __shfl_xor_sync(0xffffffffu, dot, 8);
        dot += __shfl_xor_sync(0xffffffffu, dot, 4);
        dot += __shfl_xor_sync(0xffffffffu, dot, 2);
        dot += __shfl_xor_sync(0xffffffffu, dot, 1);

        const float sc = LAM_W * g_S[row];
        float4 o4;
        o4.x = fmaf(-sc, g.x, a.x);
        o4.y = fmaf(-sc, g.y, a.y);
        o4.z = fmaf(-sc, g.z, a.z);
        o4.w = fmaf(-sc, g.w, a.w);
        ((float4*)out_assoc)[(size_t)row * 16 + l] = o4;

        if (l == 0) g_coef[row] = -dot * g_SB[row];
    }
}

// ================= K4: attention gradient + update ============================
// block handles 4 batches; 256 threads = 128 dims x 2 r-halves. grid = 256.
__global__ void __launch_bounds__(256) k4_attn(const float* __restrict__ z,
                                               const float* __restrict__ attn,
                                               const float* __restrict__ rbf,
                                               float* __restrict__ out_attn)
{
    __shared__ __align__(16) float sc[4][512];
    __shared__ float sred[4][128];

    const int tid  = threadIdx.x;
    const int j    = tid & 127;
    const int rh   = tid >> 7;
    const int bblk = blockIdx.x << 2;

    // load coef tile: 4*512 = 2048 floats = 512 float4, 2 per thread
    {
        const float4* src = (const float4*)(g_coef + bblk * Rn);
        float4* dst = (float4*)&sc[0][0];
        dst[tid]       = src[tid];
        dst[tid + 256] = src[tid + 256];
    }
    float zr[4];
#pragma unroll
    for (int tb = 0; tb < 4; ++tb) zr[tb] = z[(bblk + tb) * Dn + j];
    __syncthreads();

    float acc[4];
#pragma unroll
    for (int tb = 0; tb < 4; ++tb) acc[tb] = 0.f;

    const int r0 = rh * 256;
#pragma unroll 2
    for (int r = r0; r < r0 + 256; r += 4) {
        const float rv0 = rbf[(r + 0) * Dn + j];
        const float rv1 = rbf[(r + 1) * Dn + j];
        const float rv2 = rbf[(r + 2) * Dn + j];
        const float rv3 = rbf[(r + 3) * Dn + j];
#pragma unroll
        for (int tb = 0; tb < 4; ++tb) {
            const float4 c = *(const float4*)&sc[tb][r];
            float t;
            t = zr[tb] - rv0; acc[tb] = fmaf(c.x * t, t, acc[tb]);
            t = zr[tb] - rv1; acc[tb] = fmaf(c.y * t, t, acc[tb]);
            t = zr[tb] - rv2; acc[tb] = fmaf(c.z * t, t, acc[tb]);
            t = zr[tb] - rv3; acc[tb] = fmaf(c.w * t, t, acc[tb]);
        }
    }

    if (rh == 1) {
#pragma unroll
        for (int tb = 0; tb < 4; ++tb) sred[tb][j] = acc[tb];
    }
    __syncthreads();
    if (rh == 0) {
#pragma unroll
        for (int tb = 0; tb < 4; ++tb) {
            const int b = bblk + tb;
            const float dl = acc[tb] + sred[tb][j];
            out_attn[b * Dn + j] = fmaxf(fmaf(-LAM_A, dl, attn[b * Dn + j]), 0.f);
        }
    }
}

// ================= launch ======================================================
extern "C" void kernel_launch(void* const* d_in, const int* in_sizes, int n_in,
                              void* d_out, int out_size)
{
    const float* z      = (const float*)d_in[0];  // (B,D)
    const float* onehot = (const float*)d_in[1];  // (B,O)
    const float* attn   = (const float*)d_in[2];  // (B,D)
    const float* assoc  = (const float*)d_in[3];  // (B,R,O)
    const float* rbf    = (const float*)d_in[4];  // (R,D)

    float* out       = (float*)d_out;
    float* out_x     = out;                      // B*O
    float* out_attn  = out + Bn * On;            // B*D
    float* out_assoc = out + Bn * On + Bn * Dn;  // B*R*O

    k1_rbf  <<<dim3(Rn / 64, Bn / 32), 256>>>(z, attn, rbf);
    k2_xout <<<Bn, 256>>>(assoc, onehot, out_x);
    k3_assoc<<<2048, 256>>>(assoc, out_assoc);
    k4_attn <<<Bn / 4, 256>>>(z, attn, rbf, out_attn);
}

// round 3
// speedup vs baseline: 1.1389x; 1.0943x over previous
#include <cuda_runtime.h>
#include <math.h>

#define Bn 1024
#define Rn 512
#define Dn 128
#define On 64

#define BETA   6.5f
#define LAM_A  0.0033f
#define LAM_W  0.003f

// ---------------- scratch (device globals; no allocation allowed) -------------
__device__ __align__(16) float g_S[Bn * Rn];       // s[b,r] = exp(-beta*d)
__device__ __align__(16) float g_SB[Bn * Rn];      // beta*s*0.5/d
__device__ __align__(16) float g_G[Bn * On];       // dL/dx_out
__device__ __align__(16) float g_coef[Bn * Rn];    // -T[b,r]*SB[b,r]
__device__ __align__(16) float g_pa[4][Bn * Dn];   // k4 split-K partials

// ================= K1: RBF activations s[b,r] ==================================
// block tile 32 r x 32 b, 256 threads, 2x2 micro-tile, D tiled by 32.
// grid = (512/32) x (1024/32) = 16 x 32 = 512 blocks.
__global__ void __launch_bounds__(256) k1_rbf(const float* __restrict__ z,
                                              const float* __restrict__ attn,
                                              const float* __restrict__ rbf)
{
    __shared__ float sr[32][33];
    __shared__ float sz[32][33];
    __shared__ float sa[32][33];

    const int tid  = threadIdx.x;
    const int tr   = tid & 15;      // r lane
    const int tb   = tid >> 4;      // b lane (0..15)
    const int rblk = blockIdx.x << 5;
    const int bblk = blockIdx.y << 5;

    float acc[2][2];
#pragma unroll
    for (int i = 0; i < 2; ++i)
#pragma unroll
        for (int j = 0; j < 2; ++j) acc[i][j] = 0.f;

    // loader mapping: 32 rows x 32 cols = 1024 floats, 4 per thread (1 float4)
    const int lrow = tid >> 3;          // 0..31
    const int lcol = (tid & 7) << 2;    // 0..28

    for (int kc = 0; kc < 4; ++kc) {
        __syncthreads();
        const int goff = kc * 32 + lcol;
        float4 r0 = *(const float4*)(rbf  + (rblk + lrow) * Dn + goff);
        float4 z0 = *(const float4*)(z    + (bblk + lrow) * Dn + goff);
        float4 a0 = *(const float4*)(attn + (bblk + lrow) * Dn + goff);
        sr[lrow][lcol + 0] = r0.x; sr[lrow][lcol + 1] = r0.y;
        sr[lrow][lcol + 2] = r0.z; sr[lrow][lcol + 3] = r0.w;
        sz[lrow][lcol + 0] = z0.x; sz[lrow][lcol + 1] = z0.y;
        sz[lrow][lcol + 2] = z0.z; sz[lrow][lcol + 3] = z0.w;
        sa[lrow][lcol + 0] = a0.x; sa[lrow][lcol + 1] = a0.y;
        sa[lrow][lcol + 2] = a0.z; sa[lrow][lcol + 3] = a0.w;
        __syncthreads();

#pragma unroll 8
        for (int d = 0; d < 32; ++d) {
            float rv[2], zv[2], av[2];
#pragma unroll
            for (int i = 0; i < 2; ++i) rv[i] = sr[tr + 16 * i][d];
#pragma unroll
            for (int j = 0; j < 2; ++j) { zv[j] = sz[tb + 16 * j][d]; av[j] = sa[tb + 16 * j][d]; }
#pragma unroll
            for (int j = 0; j < 2; ++j)
#pragma unroll
                for (int i = 0; i < 2; ++i) {
                    float t = zv[j] - rv[i];
                    acc[i][j] = fmaf(av[j] * t, t, acc[i][j]);
                }
        }
    }

#pragma unroll
    for (int j = 0; j < 2; ++j) {
        const int b = bblk + tb + 16 * j;
#pragma unroll
        for (int i = 0; i < 2; ++i) {
            const int r = rblk + tr + 16 * i;
            float d2 = acc[i][j];
            float dd = sqrtf(d2);
            float s  = expf(-BETA * dd);
            g_S[b * Rn + r]  = s;
            g_SB[b * Rn + r] = (0.5f * BETA) * s / dd;
        }
    }
}

// ================= K2: x_out, teacher error G =================================
__global__ void __launch_bounds__(256) k2_xout(const float* __restrict__ assoc,
                                               const float* __restrict__ onehot,
                                               float* __restrict__ out_x)
{
    __shared__ float sS[Rn];
    __shared__ __align__(16) float4 part[16][16];

    const int b   = blockIdx.x;
    const int tid = threadIdx.x;
    sS[tid]       = g_S[b * Rn + tid];
    sS[tid + 256] = g_S[b * Rn + tid + 256];
    __syncthreads();

    const int oq = tid & 15;   // o quad
    const int rg = tid >> 4;   // r group
    float4 acc = make_float4(0.f, 0.f, 0.f, 0.f);
    const float4* arow = (const float4*)assoc + (size_t)b * (Rn * On / 4);

#pragma unroll 4
    for (int r = rg; r < Rn; r += 16) {
        float  s = sS[r];
        float4 a = arow[r * 16 + oq];
        acc.x = fmaf(s, a.x, acc.x);
        acc.y = fmaf(s, a.y, acc.y);
        acc.z = fmaf(s, a.z, acc.z);
        acc.w = fmaf(s, a.w, acc.w);
    }
    part[rg][oq] = acc;
    __syncthreads();

    if (rg == 0) {
        float4 t = part[0][oq];
#pragma unroll
        for (int k = 1; k < 16; ++k) {
            float4 p = part[k][oq];
            t.x += p.x; t.y += p.y; t.z += p.z; t.w += p.w;
        }
        float xs[4] = {t.x, t.y, t.z, t.w};
#pragma unroll
        for (int c = 0; c < 4; ++c) {
            const int o = oq * 4 + c;
            float x   = xs[c];
            float lab = onehot[b * On + o];
            float tmin  = fminf(-1.f, x);
            float teach = tmin - lab * tmin + lab * fmaxf(1.f, x);
            float e  = teach - x;
            float gd = (1.f - lab) * (x < -1.f ? 1.f : 0.f) + lab * (x > 1.f ? 1.f : 0.f);
            float G  = 0.03125f * e * (gd - 1.f);   // (2/O)*e*(dT/dx - 1)
            g_G[b * On + o]   = G;
            out_x[b * On + o] = 2.f * x;            // PHI = 2
        }
    }
}

// ================= K3: assoc update + dL/ds (fused) ===========================
// REVERSED traversal: k2 left the tail of assoc resident in L2; start there.
__global__ void __launch_bounds__(256) k3_assoc(const float* __restrict__ assoc,
                                                float* __restrict__ out_assoc)
{
    const int lane = threadIdx.x & 31;
    const int half = lane >> 4;
    const int l    = lane & 15;
    const int gw   = (blockIdx.x * blockDim.x + threadIdx.x) >> 5;
    const int nw   = (gridDim.x * blockDim.x) >> 5;
    const int total = Bn * Rn;

    for (int it = gw * 2 + half; it < total; it += nw * 2) {
        const int row = total - 1 - it;
        const int b = row >> 9;
        const float4 a = ((const float4*)assoc)[(size_t)row * 16 + l];
        const float4 g = ((const float4*)g_G)[b * 16 + l];

        float dot = a.x * g.x;
        dot = fmaf(a.y, g.y, dot);
        dot = fmaf(a.z, g.z, dot);
        dot = fmaf(a.w, g.w, dot);
        dot += __shfl_xor_sync(0xffffffffu, dot, 8);
        dot += __shfl_xor_sync(0xffffffffu, dot, 4);
        dot += __shfl_xor_sync(0xffffffffu, dot, 2);
        dot += __shfl_xor_sync(0xffffffffu, dot, 1);

        const float sc = LAM_W * g_S[row];
        float4 o4;
        o4.x = fmaf(-sc, g.x, a.x);
        o4.y = fmaf(-sc, g.y, a.y);
        o4.z = fmaf(-sc, g.z, a.z);
        o4.w = fmaf(-sc, g.w, a.w);
        ((float4*)out_assoc)[(size_t)row * 16 + l] = o4;

        if (l == 0) g_coef[row] = -dot * g_SB[row];
    }
}

// ================= K4: attention gradient (split-K partials) ===================
// grid (Bn/4, 4): blockIdx.x = 4-batch group, blockIdx.y = 128-wide r chunk.
// 256 threads = 128 dims x 2 r-halves (64 r each).
__global__ void __launch_bounds__(256) k4_attn(const float* __restrict__ z,
                                               const float* __restrict__ rbf)
{
    __shared__ __align__(16) float sc[4][128];
    __shared__ float sred[4][128];

    const int tid   = threadIdx.x;
    const int j     = tid & 127;
    const int rh    = tid >> 7;
    const int bblk  = blockIdx.x << 2;
    const int rbase = blockIdx.y << 7;

    // load coef chunk: 4 batches x 128 r = 512 floats
#pragma unroll
    for (int i = tid; i < 512; i += 256) {
        const int tb = i >> 7;
        const int r  = i & 127;
        sc[tb][r] = g_coef[(bblk + tb) * Rn + rbase + r];
    }
    float zr[4];
#pragma unroll
    for (int tb = 0; tb < 4; ++tb) zr[tb] = z[(bblk + tb) * Dn + j];
    __syncthreads();

    float acc[4];
#pragma unroll
    for (int tb = 0; tb < 4; ++tb) acc[tb] = 0.f;

    const int r0 = rh * 64;
#pragma unroll 4
    for (int r = r0; r < r0 + 64; r += 4) {
        const float rv0 = rbf[(rbase + r + 0) * Dn + j];
        const float rv1 = rbf[(rbase + r + 1) * Dn + j];
        const float rv2 = rbf[(rbase + r + 2) * Dn + j];
        const float rv3 = rbf[(rbase + r + 3) * Dn + j];
#pragma unroll
        for (int tb = 0; tb < 4; ++tb) {
            const float4 c = *(const float4*)&sc[tb][r];
            float t;
            t = zr[tb] - rv0; acc[tb] = fmaf(c.x * t, t, acc[tb]);
            t = zr[tb] - rv1; acc[tb] = fmaf(c.y * t, t, acc[tb]);
            t = zr[tb] - rv2; acc[tb] = fmaf(c.z * t, t, acc[tb]);
            t = zr[tb] - rv3; acc[tb] = fmaf(c.w * t, t, acc[tb]);
        }
    }

    if (rh == 1) {
#pragma unroll
        for (int tb = 0; tb < 4; ++tb) sred[tb][j] = acc[tb];
    }
    __syncthreads();
    if (rh == 0) {
        float* pa = g_pa[blockIdx.y];
#pragma unroll
        for (int tb = 0; tb < 4; ++tb)
            pa[(bblk + tb) * Dn + j] = acc[tb] + sred[tb][j];
    }
}

// ================= K5: reduce partials + attention update ======================
__global__ void __launch_bounds__(256) k5_attn_fin(const float* __restrict__ attn,
                                                   float* __restrict__ out_attn)
{
    const int i = blockIdx.x * 256 + threadIdx.x;   // float4 index, total 32768
    const float4 a  = ((const float4*)attn)[i];
    const float4 p0 = ((const float4*)g_pa[0])[i];
    const float4 p1 = ((const float4*)g_pa[1])[i];
    const float4 p2 = ((const float4*)g_pa[2])[i];
    const float4 p3 = ((const float4*)g_pa[3])[i];
    float4 o;
    o.x = fmaxf(fmaf(-LAM_A, (p0.x + p1.x) + (p2.x + p3.x), a.x), 0.f);
    o.y = fmaxf(fmaf(-LAM_A, (p0.y + p1.y) + (p2.y + p3.y), a.y), 0.f);
    o.z = fmaxf(fmaf(-LAM_A, (p0.z + p1.z) + (p2.z + p3.z), a.z), 0.f);
    o.w = fmaxf(fmaf(-LAM_A, (p0.w + p1.w) + (p2.w + p3.w), a.w), 0.f);
    ((float4*)out_attn)[i] = o;
}

// ================= launch ======================================================
extern "C" void kernel_launch(void* const* d_in, const int* in_sizes, int n_in,
                              void* d_out, int out_size)
{
    const float* z      = (const float*)d_in[0];  // (B,D)
    const float* onehot = (const float*)d_in[1];  // (B,O)
    const float* attn   = (const float*)d_in[2];  // (B,D)
    const float* assoc  = (const float*)d_in[3];  // (B,R,O)
    const float* rbf    = (const float*)d_in[4];  // (R,D)

    float* out       = (float*)d_out;
    float* out_x     = out;                      // B*O
    float* out_attn  = out + Bn * On;            // B*D
    float* out_assoc = out + Bn * On + Bn * Dn;  // B*R*O

    k1_rbf  <<<dim3(Rn / 32, Bn / 32), 256>>>(z, attn, rbf);
    k2_xout <<<Bn, 256>>>(assoc, onehot, out_x);
    k3_assoc<<<2048, 256>>>(assoc, out_assoc);
    k4_attn <<<dim3(Bn / 4, 4), 256>>>(z, rbf);
    k5_attn_fin<<<(Bn * Dn / 4) / 256, 256>>>(attn, out_attn);
}

// round 4
// speedup vs baseline: 1.2318x; 1.0816x over previous
#include <cuda_runtime.h>
#include <math.h>

#define Bn 1024
#define Rn 512
#define Dn 128
#define On 64

#define BETA   6.5f
#define LAM_A  0.0033f
#define LAM_W  0.003f

#define K4_CHUNKS 8

// ---------------- scratch (device globals; no allocation allowed) -------------
__device__ __align__(16) float g_S[Bn * Rn];             // s[b,r]
__device__ __align__(16) float g_SB[Bn * Rn];            // beta*s*0.5/d
__device__ __align__(16) float g_coef[Bn * Rn];          // -T[b,r]*SB[b,r]
__device__ __align__(16) float g_pa[K4_CHUNKS][Bn * Dn]; // k4 split-K partials

// ================= K1: RBF activations s[b,r] ==================================
// block tile 32 r x 32 b, 256 threads, 2x2 micro-tile, D tiled by 32. grid=512.
__global__ void __launch_bounds__(256) k1_rbf(const float* __restrict__ z,
                                              const float* __restrict__ attn,
                                              const float* __restrict__ rbf)
{
    __shared__ float sr[32][33];
    __shared__ float sz[32][33];
    __shared__ float sa[32][33];

    const int tid  = threadIdx.x;
    const int tr   = tid & 15;
    const int tb   = tid >> 4;
    const int rblk = blockIdx.x << 5;
    const int bblk = blockIdx.y << 5;

    float acc[2][2];
#pragma unroll
    for (int i = 0; i < 2; ++i)
#pragma unroll
        for (int j = 0; j < 2; ++j) acc[i][j] = 0.f;

    const int lrow = tid >> 3;
    const int lcol = (tid & 7) << 2;

    for (int kc = 0; kc < 4; ++kc) {
        __syncthreads();
        const int goff = kc * 32 + lcol;
        float4 r0 = *(const float4*)(rbf  + (rblk + lrow) * Dn + goff);
        float4 z0 = *(const float4*)(z    + (bblk + lrow) * Dn + goff);
        float4 a0 = *(const float4*)(attn + (bblk + lrow) * Dn + goff);
        sr[lrow][lcol + 0] = r0.x; sr[lrow][lcol + 1] = r0.y;
        sr[lrow][lcol + 2] = r0.z; sr[lrow][lcol + 3] = r0.w;
        sz[lrow][lcol + 0] = z0.x; sz[lrow][lcol + 1] = z0.y;
        sz[lrow][lcol + 2] = z0.z; sz[lrow][lcol + 3] = z0.w;
        sa[lrow][lcol + 0] = a0.x; sa[lrow][lcol + 1] = a0.y;
        sa[lrow][lcol + 2] = a0.z; sa[lrow][lcol + 3] = a0.w;
        __syncthreads();

#pragma unroll 8
        for (int d = 0; d < 32; ++d) {
            float rv[2], zv[2], av[2];
#pragma unroll
            for (int i = 0; i < 2; ++i) rv[i] = sr[tr + 16 * i][d];
#pragma unroll
            for (int j = 0; j < 2; ++j) { zv[j] = sz[tb + 16 * j][d]; av[j] = sa[tb + 16 * j][d]; }
#pragma unroll
            for (int j = 0; j < 2; ++j)
#pragma unroll
                for (int i = 0; i < 2; ++i) {
                    float t = zv[j] - rv[i];
                    acc[i][j] = fmaf(av[j] * t, t, acc[i][j]);
                }
        }
    }

#pragma unroll
    for (int j = 0; j < 2; ++j) {
        const int b = bblk + tb + 16 * j;
#pragma unroll
        for (int i = 0; i < 2; ++i) {
            const int r = rblk + tr + 16 * i;
            float d2 = acc[i][j];
            float dd = sqrtf(d2);
            float s  = expf(-BETA * dd);
            g_S[b * Rn + r]  = s;
            g_SB[b * Rn + r] = (0.5f * BETA) * s / dd;
        }
    }
}

// ================= K23: fused x_out/G + assoc update + dL/ds ===================
// one block per batch. phase 1 streams assoc[b] (128KB) for x_out; phase 2
// re-reads it (L2-resident; residency capped at 3 blocks/SM via smem padding)
// for the update and the dL/ds dot.
extern __shared__ float k23_pad[];  // padding only (occupancy control)
__global__ void __launch_bounds__(256) k23_fused(const float* __restrict__ assoc,
                                                 const float* __restrict__ onehot,
                                                 float* __restrict__ out_x,
                                                 float* __restrict__ out_assoc)
{
    __shared__ float sS[Rn];
    __shared__ __align__(16) float4 part[16][16];
    __shared__ __align__(16) float4 sG[16];

    const int b   = blockIdx.x;
    const int tid = threadIdx.x;
    sS[tid]       = g_S[b * Rn + tid];
    sS[tid + 256] = g_S[b * Rn + tid + 256];
    __syncthreads();

    const int oq = tid & 15;   // o quad
    const int rg = tid >> 4;   // r group
    const float4* arow = (const float4*)assoc + (size_t)b * (Rn * On / 4);

    // ---- phase 1: x_out ----
    float4 acc = make_float4(0.f, 0.f, 0.f, 0.f);
#pragma unroll 4
    for (int r = rg; r < Rn; r += 16) {
        float  s = sS[r];
        float4 a = arow[r * 16 + oq];
        acc.x = fmaf(s, a.x, acc.x);
        acc.y = fmaf(s, a.y, acc.y);
        acc.z = fmaf(s, a.z, acc.z);
        acc.w = fmaf(s, a.w, acc.w);
    }
    part[rg][oq] = acc;
    __syncthreads();

    if (rg == 0) {
        float4 t = part[0][oq];
#pragma unroll
        for (int k = 1; k < 16; ++k) {
            float4 p = part[k][oq];
            t.x += p.x; t.y += p.y; t.z += p.z; t.w += p.w;
        }
        float xs[4] = {t.x, t.y, t.z, t.w};
        float Gs[4];
#pragma unroll
        for (int c = 0; c < 4; ++c) {
            const int o = oq * 4 + c;
            float x   = xs[c];
            float lab = onehot[b * On + o];
            float tmin  = fminf(-1.f, x);
            float teach = tmin - lab * tmin + lab * fmaxf(1.f, x);
            float e  = teach - x;
            float gd = (1.f - lab) * (x < -1.f ? 1.f : 0.f) + lab * (x > 1.f ? 1.f : 0.f);
            Gs[c] = 0.03125f * e * (gd - 1.f);   // (2/O)*e*(dT/dx - 1)
            out_x[b * On + o] = 2.f * x;         // PHI = 2
        }
        sG[oq] = make_float4(Gs[0], Gs[1], Gs[2], Gs[3]);
    }
    __syncthreads();

    // ---- phase 2: assoc update + dL/ds (reads hit L2) ----
    const float4 g = sG[oq];
    float4* orow = (float4*)out_assoc + (size_t)b * (Rn * On / 4);
    const float* sbrow = g_SB + b * Rn;
    float* crow = g_coef + b * Rn;

#pragma unroll 4
    for (int r = rg; r < Rn; r += 16) {
        const float4 a = arow[r * 16 + oq];

        float dot = a.x * g.x;
        dot = fmaf(a.y, g.y, dot);
        dot = fmaf(a.z, g.z, dot);
        dot = fmaf(a.w, g.w, dot);
        dot += __shfl_xor_sync(0xffffffffu, dot, 8);
        dot += __shfl_xor_sync(0xffffffffu, dot, 4);
        dot += __shfl_xor_sync(0xffffffffu, dot, 2);
        dot += __shfl_xor_sync(0xffffffffu, dot, 1);

        const float sc = LAM_W * sS[r];
        float4 o4;
        o4.x = fmaf(-sc, g.x, a.x);
        o4.y = fmaf(-sc, g.y, a.y);
        o4.z = fmaf(-sc, g.z, a.z);
        o4.w = fmaf(-sc, g.w, a.w);
        orow[r * 16 + oq] = o4;

        if (oq == 0) crow[r] = -dot * sbrow[r];
    }
}

// ================= K4: attention gradient (split-K partials) ===================
// grid (Bn/4, 8): 64-wide r chunks. 256 threads = 128 dims x 2 r-halves.
__global__ void __launch_bounds__(256) k4_attn(const float* __restrict__ z,
                                               const float* __restrict__ rbf)
{
    __shared__ __align__(16) float sc[4][64];
    __shared__ float sred[4][128];

    const int tid   = threadIdx.x;
    const int j     = tid & 127;
    const int rh    = tid >> 7;
    const int bblk  = blockIdx.x << 2;
    const int rbase = blockIdx.y << 6;

    if (tid < 256) {
        const int tb = tid >> 6;
        const int r  = tid & 63;
        sc[tb][r] = g_coef[(bblk + tb) * Rn + rbase + r];
    }
    float zr[4];
#pragma unroll
    for (int tb = 0; tb < 4; ++tb) zr[tb] = z[(bblk + tb) * Dn + j];
    __syncthreads();

    float acc[4];
#pragma unroll
    for (int tb = 0; tb < 4; ++tb) acc[tb] = 0.f;

    const int r0 = rh * 32;
#pragma unroll 4
    for (int r = r0; r < r0 + 32; r += 4) {
        const float rv0 = rbf[(rbase + r + 0) * Dn + j];
        const float rv1 = rbf[(rbase + r + 1) * Dn + j];
        const float rv2 = rbf[(rbase + r + 2) * Dn + j];
        const float rv3 = rbf[(rbase + r + 3) * Dn + j];
#pragma unroll
        for (int tb = 0; tb < 4; ++tb) {
            const float4 c = *(const float4*)&sc[tb][r];
            float t;
            t = zr[tb] - rv0; acc[tb] = fmaf(c.x * t, t, acc[tb]);
            t = zr[tb] - rv1; acc[tb] = fmaf(c.y * t, t, acc[tb]);
            t = zr[tb] - rv2; acc[tb] = fmaf(c.z * t, t, acc[tb]);
            t = zr[tb] - rv3; acc[tb] = fmaf(c.w * t, t, acc[tb]);
        }
    }

    if (rh == 1) {
#pragma unroll
        for (int tb = 0; tb < 4; ++tb) sred[tb][j] = acc[tb];
    }
    __syncthreads();
    if (rh == 0) {
        float* pa = g_pa[blockIdx.y];
#pragma unroll
        for (int tb = 0; tb < 4; ++tb)
            pa[(bblk + tb) * Dn + j] = acc[tb] + sred[tb][j];
    }
}

// ================= K5: reduce partials + attention update ======================
__global__ void __launch_bounds__(256) k5_attn_fin(const float* __restrict__ attn,
                                                   float* __restrict__ out_attn)
{
    const int i = blockIdx.x * 256 + threadIdx.x;   // float4 index, total 32768
    const float4 a = ((const float4*)attn)[i];
    float sx = 0.f, sy = 0.f, sz = 0.f, sw = 0.f;
#pragma unroll
    for (int k = 0; k < K4_CHUNKS; ++k) {
        const float4 p = ((const float4*)g_pa[k])[i];
        sx += p.x; sy += p.y; sz += p.z; sw += p.w;
    }
    float4 o;
    o.x = fmaxf(fmaf(-LAM_A, sx, a.x), 0.f);
    o.y = fmaxf(fmaf(-LAM_A, sy, a.y), 0.f);
    o.z = fmaxf(fmaf(-LAM_A, sz, a.z), 0.f);
    o.w = fmaxf(fmaf(-LAM_A, sw, a.w), 0.f);
    ((float4*)out_attn)[i] = o;
}

// ================= launch ======================================================
extern "C" void kernel_launch(void* const* d_in, const int* in_sizes, int n_in,
                              void* d_out, int out_size)
{
    const float* z      = (const float*)d_in[0];  // (B,D)
    const float* onehot = (const float*)d_in[1];  // (B,O)
    const float* attn   = (const float*)d_in[2];  // (B,D)
    const float* assoc  = (const float*)d_in[3];  // (B,R,O)
    const float* rbf    = (const float*)d_in[4];  // (R,D)

    float* out       = (float*)d_out;
    float* out_x     = out;                      // B*O
    float* out_attn  = out + Bn * On;            // B*D
    float* out_assoc = out + Bn * On + Bn * Dn;  // B*R*O

    // residency cap for k23 (3 blocks/SM): 56KB dynamic smem padding.
    const int K23_PAD = 56 * 1024;
    cudaFuncSetAttribute(k23_fused, cudaFuncAttributeMaxDynamicSharedMemorySize, K23_PAD);

    k1_rbf    <<<dim3(Rn / 32, Bn / 32), 256>>>(z, attn, rbf);
    k23_fused <<<Bn, 256, K23_PAD>>>(assoc, onehot, out_x, out_assoc);
    k4_attn   <<<dim3(Bn / 4, K4_CHUNKS), 256>>>(z, rbf);
    k5_attn_fin<<<(Bn * Dn / 4) / 256, 256>>>(attn, out_attn);
}